// round 16
// baseline (speedup 1.0000x reference)
#include <cuda_runtime.h>
#include <cuda_bf16.h>
#include <math.h>
#include <stdint.h>

#define B_  4
#define S_  2048
#define D_  1024
#define H_  16
#define HD_ 64

// Scratch (allocation-free rule). Referenced ONLY from device code.
// g_qkv[0]: Q [b,h][s][hd]  g_qkv[1]: K [b,h][s][hd]  g_qkv[2]: V^T [b,h][hd][s]
__device__ float g_qkv[3][(size_t)B_ * H_ * S_ * HD_];
__device__ float g_ctx[(size_t)B_ * S_ * D_];

// ---------------------------------------------------------------------------
// helpers
// ---------------------------------------------------------------------------
__device__ __forceinline__ uint32_t prmt_hi(uint32_t a, uint32_t b) {
    uint32_t d;
    asm("prmt.b32 %0, %1, %2, 0x7632;" : "=r"(d) : "r"(a), "r"(b));
    return d;
}
__device__ __forceinline__ uint32_t cvt_bf16x2(float hi_val, float lo_val) {
    uint32_t d;
    asm("cvt.rn.bf16x2.f32 %0, %1, %2;" : "=r"(d) : "f"(hi_val), "f"(lo_val));
    return d;
}
__device__ __forceinline__ float ex2_(float x) {
    float y;
    asm("ex2.approx.ftz.f32 %0, %1;" : "=f"(y) : "f"(x));
    return y;
}
__device__ __forceinline__ void mma_bf16(float& c0, float& c1, float& c2, float& c3,
                                         uint32_t a0, uint32_t a1, uint32_t a2, uint32_t a3,
                                         uint32_t b0, uint32_t b1) {
    asm volatile(
        "mma.sync.aligned.m16n8k16.row.col.f32.bf16.bf16.f32 "
        "{%0,%1,%2,%3},{%4,%5,%6,%7},{%8,%9},{%0,%1,%2,%3};"
        : "+f"(c0), "+f"(c1), "+f"(c2), "+f"(c3)
        : "r"(a0), "r"(a1), "r"(a2), "r"(a3), "r"(b0), "r"(b1));
}

#define SROW 12
// stage layout (words): Ah[3072] Al[3072] Bh[1536] Bl[1536] = 9216 words/stage
#define ST_AL 3072
#define ST_BH 6144
#define ST_BL 7680
#define ST_WORDS 9216

__device__ __forceinline__ void split_store_row(uint32_t* Hh, uint32_t* Hl, int idx, float4 v) {
    const uint32_t bx = __float_as_uint(v.x), by = __float_as_uint(v.y);
    const uint32_t bz = __float_as_uint(v.z), bw = __float_as_uint(v.w);
    Hh[idx]     = prmt_hi(bx, by);
    Hh[idx + 1] = prmt_hi(bz, bw);
    Hl[idx]     = cvt_bf16x2(v.y - __uint_as_float(by & 0xffff0000u),
                             v.x - __uint_as_float(bx & 0xffff0000u));
    Hl[idx + 1] = cvt_bf16x2(v.w - __uint_as_float(bw & 0xffff0000u),
                             v.z - __uint_as_float(bz & 0xffff0000u));
}

__device__ __forceinline__ void stage_B(uint32_t* st, int bn4, int bk2,
                                        float4 v0, float4 v1) {
    uint32_t* BhS = st + ST_BH;
    uint32_t* BlS = st + ST_BL;
    const float e[4] = {v0.x, v0.y, v0.z, v0.w};
    const float o[4] = {v1.x, v1.y, v1.z, v1.w};
#pragma unroll
    for (int j = 0; j < 4; j++) {
        const uint32_t be = __float_as_uint(e[j]), bo = __float_as_uint(o[j]);
        BhS[(bn4 + j) * SROW + bk2] = prmt_hi(be, bo);
        BlS[(bn4 + j) * SROW + bk2] =
            cvt_bf16x2(o[j] - __uint_as_float(bo & 0xffff0000u),
                       e[j] - __uint_as_float(be & 0xffff0000u));
    }
}

// ---------------------------------------------------------------------------
// Kernel 1/3: tensor-core GEMM — 256x128 tile, double-buffered, pass-major,
// now 512 threads = 16 warps (4M x 4N, warp tile 64x32) for 2x latency cover.
// ---------------------------------------------------------------------------
template <int LDN, int MODE>
__global__ __launch_bounds__(512) void tc_gemm(const float* __restrict__ Xarg,
                                               const float* __restrict__ W,
                                               const float* __restrict__ bias,
                                               float* __restrict__ out) {
    extern __shared__ uint32_t smg[];   // 2 x 36KB stages

    const float* __restrict__ X = (MODE == 0) ? Xarg : (const float*)g_ctx;

    const int tid = threadIdx.x;
    const int lane = tid & 31;
    const int wid = tid >> 5;         // 0..15
    const int wm = wid >> 2;          // 0..3 : 64-row band
    const int wn = wid & 3;           // 0..3 : 32-col band
    const int grp = lane >> 2;
    const int tig = lane & 3;
    const int m0 = blockIdx.y * 256;
    const int n0 = blockIdx.x * 128;

    float acc[4][4][4];
#pragma unroll
    for (int mi = 0; mi < 4; mi++)
#pragma unroll
        for (int ni = 0; ni < 4; ni++)
#pragma unroll
            for (int r = 0; r < 4; r++) acc[mi][ni][r] = 0.f;

    // A loader: 512 threads x 2 rows (rows (tid&255)>>2 + (tid>>8)*128 + {0,64})
    const int arow = ((tid & 255) >> 2) + (tid >> 8) * 128;
    const int ak2 = (tid & 3) * 2;
    // B loader: threads 0..255 only (same pattern as R14)
    const int bk2 = tid & 7;
    const int bn4 = ((tid >> 3) & 31) * 4;

    const int a_base = (wm * 64 + grp) * SROW + tig;
    const int b_base = (wn * 32 + grp) * SROW + tig;

    const float* Xp = X + (size_t)(m0 + arow) * 1024 + ak2 * 2;
    const float* Wp0 = W + (size_t)(2 * bk2) * LDN + n0 + bn4;
    const float* Wp1 = W + (size_t)(2 * bk2 + 1) * LDN + n0 + bn4;
    const bool do_b = (tid < 256);

    // ---- prologue: load tile 0, stage into buffer 0 ----
    float4 a_pre0 = *(const float4*)(Xp);
    float4 a_pre1 = *(const float4*)(Xp + (size_t)64 * 1024);
    float4 b_pre0, b_pre1;
    if (do_b) {
        b_pre0 = *(const float4*)(Wp0);
        b_pre1 = *(const float4*)(Wp1);
    }
    split_store_row(smg, smg + ST_AL, (arow + 0) * SROW + ak2, a_pre0);
    split_store_row(smg, smg + ST_AL, (arow + 64) * SROW + ak2, a_pre1);
    if (do_b) stage_B(smg, bn4, bk2, b_pre0, b_pre1);
    __syncthreads();

#pragma unroll 1
    for (int kt = 0; kt < 1024; kt += 16) {
        const int cur = (kt >> 4) & 1;
        uint32_t* stC = smg + cur * ST_WORDS;
        const bool hn = (kt + 16) < 1024;

        // ---- issue global prefetch for next k-tile ----
        if (hn) {
            const float* xp = Xp + kt + 16;
            a_pre0 = *(const float4*)(xp);
            a_pre1 = *(const float4*)(xp + (size_t)64 * 1024);
            if (do_b) {
                b_pre0 = *(const float4*)(Wp0 + (size_t)(kt + 16) * LDN);
                b_pre1 = *(const float4*)(Wp1 + (size_t)(kt + 16) * LDN);
            }
        }

        const uint32_t* AhC = stC;
        const uint32_t* AlC = stC + ST_AL;
        const uint32_t* BhC = stC + ST_BH;
        const uint32_t* BlC = stC + ST_BL;

        uint32_t bh[4][2], bl[4][2];
#pragma unroll
        for (int ni = 0; ni < 4; ni++) {
            const int bb = b_base + ni * 8 * SROW;
            bh[ni][0] = BhC[bb]; bh[ni][1] = BhC[bb + 4];
            bl[ni][0] = BlC[bb]; bl[ni][1] = BlC[bb + 4];
        }

#pragma unroll
        for (int mi = 0; mi < 4; mi++) {
            const int ab = a_base + mi * 16 * SROW;
            const uint32_t ah0 = AhC[ab];
            const uint32_t ah1 = AhC[ab + 8 * SROW];
            const uint32_t ah2 = AhC[ab + 4];
            const uint32_t ah3 = AhC[ab + 8 * SROW + 4];
            const uint32_t al0 = AlC[ab];
            const uint32_t al1 = AlC[ab + 8 * SROW];
            const uint32_t al2 = AlC[ab + 4];
            const uint32_t al3 = AlC[ab + 8 * SROW + 4];

            // pass-major: 4 independent MMAs per pass
#pragma unroll
            for (int ni = 0; ni < 4; ni++)
                mma_bf16(acc[mi][ni][0], acc[mi][ni][1], acc[mi][ni][2], acc[mi][ni][3],
                         ah0, ah1, ah2, ah3, bh[ni][0], bh[ni][1]);
#pragma unroll
            for (int ni = 0; ni < 4; ni++)
                mma_bf16(acc[mi][ni][0], acc[mi][ni][1], acc[mi][ni][2], acc[mi][ni][3],
                         ah0, ah1, ah2, ah3, bl[ni][0], bl[ni][1]);
#pragma unroll
            for (int ni = 0; ni < 4; ni++)
                mma_bf16(acc[mi][ni][0], acc[mi][ni][1], acc[mi][ni][2], acc[mi][ni][3],
                         al0, al1, al2, al3, bh[ni][0], bh[ni][1]);
        }

        // ---- stage next tile into the other buffer (guarded by sync) ----
        if (hn) {
            uint32_t* stN = smg + (cur ^ 1) * ST_WORDS;
            split_store_row(stN, stN + ST_AL, (arow + 0) * SROW + ak2, a_pre0);
            split_store_row(stN, stN + ST_AL, (arow + 64) * SROW + ak2, a_pre1);
            if (do_b) stage_B(stN, bn4, bk2, b_pre0, b_pre1);
        }
        __syncthreads();
    }

    // ---- epilogue ----
#pragma unroll
    for (int mi = 0; mi < 4; mi++) {
#pragma unroll
        for (int rr = 0; rr < 2; rr++) {
            const int row = m0 + wm * 64 + mi * 16 + grp + rr * 8;
#pragma unroll
            for (int ni = 0; ni < 4; ni++) {
                const int n = n0 + wn * 32 + ni * 8 + tig * 2;
                const float v0 = acc[mi][ni][rr * 2 + 0] + bias[n];
                const float v1 = acc[mi][ni][rr * 2 + 1] + bias[n + 1];
                if (MODE == 0) {
                    const int b = row >> 11, s = row & 2047;
                    const int part = n >> 10;
                    const int d1 = n & 1023;
                    const int h = d1 >> 6, hd = d1 & 63;
                    if (part == 2) {
                        float* p = &g_qkv[2][((size_t)(b * H_ + h) * HD_ + hd) * S_ + s];
                        p[0] = v0;
                        p[S_] = v1;
                    } else {
                        float* p = &g_qkv[part][((size_t)(b * H_ + h) * S_ + s) * HD_ + hd];
                        *(float2*)p = make_float2(v0, v1);
                    }
                } else {
                    *(float2*)(out + (size_t)row * 1024 + n) = make_float2(v0, v1);
                }
            }
        }
    }
}

// ---------------------------------------------------------------------------
// Kernel 2: tensor-core flash attention (FROZEN from R14-passing).
// ---------------------------------------------------------------------------
#define STR 36

__global__ __launch_bounds__(256) void flash_tc() {
    extern __shared__ uint32_t sm4[];
    uint32_t* qh = sm4;
    uint32_t* ql = qh + 128 * STR;
    uint32_t* kh = ql + 128 * STR;
    uint32_t* kl = kh + 64 * STR;
    uint32_t* vh = kl + 64 * STR;
    uint32_t* vl = vh + 64 * STR;

    const int tid = threadIdx.x;
    const int lane = tid & 31;
    const int wid = tid >> 5;
    const int grp = lane >> 2;
    const int tig = lane & 3;
    const int qt = gridDim.x - 1 - blockIdx.x;
    const int q0 = qt * 128;
    const int h = blockIdx.y, b = blockIdx.z;

    const float* Qg  = g_qkv[0] + (size_t)(b * H_ + h) * S_ * HD_;
    const float* Kg  = g_qkv[1] + (size_t)(b * H_ + h) * S_ * HD_;
    const float* Vtg = g_qkv[2] + (size_t)(b * H_ + h) * HD_ * S_;

    {
        const float cs = 0.125f * 1.4426950408889634f;
        const int r = tid >> 1, hb = (tid & 1) * 32;
        const float* src = Qg + (size_t)(q0 + r) * 64 + hb;
        uint32_t* dh = qh + r * STR + (hb >> 1);
        uint32_t* dl = ql + r * STR + (hb >> 1);
#pragma unroll
        for (int i = 0; i < 8; i++) {
            float4 v = *(const float4*)(src + 4 * i);
            v.x *= cs; v.y *= cs; v.z *= cs; v.w *= cs;
            const uint32_t bx = __float_as_uint(v.x), by = __float_as_uint(v.y);
            const uint32_t bz = __float_as_uint(v.z), bw = __float_as_uint(v.w);
            dh[2 * i]     = prmt_hi(bx, by);
            dh[2 * i + 1] = prmt_hi(bz, bw);
            dl[2 * i]     = cvt_bf16x2(v.y - __uint_as_float(by & 0xffff0000u),
                                       v.x - __uint_as_float(bx & 0xffff0000u));
            dl[2 * i + 1] = cvt_bf16x2(v.w - __uint_as_float(bw & 0xffff0000u),
                                       v.z - __uint_as_float(bz & 0xffff0000u));
        }
    }

    float m0r = -1e30f, m1r = -1e30f, l0 = 0.f, l1 = 0.f;
    float oacc[8][4];
#pragma unroll
    for (int n = 0; n < 8; n++)
#pragma unroll
        for (int r = 0; r < 4; r++) oacc[n][r] = 0.f;

    __syncthreads();

    const int row_max_w = q0 + wid * 16 + 15;
    const int ntiles = 2 * qt + 2;

#pragma unroll 1
    for (int t = 0; t < ntiles; t++) {
        const int j0 = t * 64;

        {
            const int r = tid >> 2, hb2 = (tid & 3) * 16;
            const float* src = Kg + (size_t)(j0 + r) * 64 + hb2;
            uint32_t* dh = kh + r * STR + (hb2 >> 1);
            uint32_t* dl = kl + r * STR + (hb2 >> 1);
#pragma unroll
            for (int i = 0; i < 4; i++) {
                const float4 v = *(const float4*)(src + 4 * i);
                const uint32_t bx = __float_as_uint(v.x), by = __float_as_uint(v.y);
                const uint32_t bz = __float_as_uint(v.z), bw = __float_as_uint(v.w);
                dh[2 * i]     = prmt_hi(bx, by);
                dh[2 * i + 1] = prmt_hi(bz, bw);
                dl[2 * i]     = cvt_bf16x2(v.y - __uint_as_float(by & 0xffff0000u),
                                           v.x - __uint_as_float(bx & 0xffff0000u));
                dl[2 * i + 1] = cvt_bf16x2(v.w - __uint_as_float(bw & 0xffff0000u),
                                           v.z - __uint_as_float(bz & 0xffff0000u));
            }
        }
        {
            const int d = tid >> 2, kb = (tid & 3) * 16;
            const float* src = Vtg + (size_t)d * S_ + j0 + kb;
            uint32_t* dh = vh + d * STR + (kb >> 1);
            uint32_t* dl = vl + d * STR + (kb >> 1);
#pragma unroll
            for (int i = 0; i < 4; i++) {
                const float4 v = *(const float4*)(src + 4 * i);
                const uint32_t bx = __float_as_uint(v.x), by = __float_as_uint(v.y);
                const uint32_t bz = __float_as_uint(v.z), bw = __float_as_uint(v.w);
                dh[2 * i]     = prmt_hi(bx, by);
                dh[2 * i + 1] = prmt_hi(bz, bw);
                dl[2 * i]     = cvt_bf16x2(v.y - __uint_as_float(by & 0xffff0000u),
                                           v.x - __uint_as_float(bx & 0xffff0000u));
                dl[2 * i + 1] = cvt_bf16x2(v.w - __uint_as_float(bw & 0xffff0000u),
                                           v.z - __uint_as_float(bz & 0xffff0000u));
            }
        }
        __syncthreads();

        if (row_max_w >= j0) {
            float sacc[8][4];
#pragma unroll
            for (int n = 0; n < 8; n++)
#pragma unroll
                for (int r = 0; r < 4; r++) sacc[n][r] = 0.f;

#pragma unroll
            for (int jj = 0; jj < 4; jj++) {
                const int ab = (wid * 16 + grp) * STR + 8 * jj + tig;
                const uint32_t ah0 = qh[ab];
                const uint32_t ah1 = qh[ab + 8 * STR];
                const uint32_t ah2 = qh[ab + 4];
                const uint32_t ah3 = qh[ab + 8 * STR + 4];
                const uint32_t al0 = ql[ab];
                const uint32_t al1 = ql[ab + 8 * STR];
                const uint32_t al2 = ql[ab + 4];
                const uint32_t al3 = ql[ab + 8 * STR + 4];
#pragma unroll
                for (int n = 0; n < 8; n++) {
                    const int kb = (8 * n + grp) * STR + 8 * jj + tig;
                    mma_bf16(sacc[n][0], sacc[n][1], sacc[n][2], sacc[n][3],
                             ah0, ah1, ah2, ah3, kh[kb], kh[kb + 4]);
                }
#pragma unroll
                for (int n = 0; n < 8; n++) {
                    const int kb = (8 * n + grp) * STR + 8 * jj + tig;
                    mma_bf16(sacc[n][0], sacc[n][1], sacc[n][2], sacc[n][3],
                             ah0, ah1, ah2, ah3, kl[kb], kl[kb + 4]);
                }
#pragma unroll
                for (int n = 0; n < 8; n++) {
                    const int kb = (8 * n + grp) * STR + 8 * jj + tig;
                    mma_bf16(sacc[n][0], sacc[n][1], sacc[n][2], sacc[n][3],
                             al0, al1, al2, al3, kh[kb], kh[kb + 4]);
                }
            }

            const int row0 = q0 + wid * 16 + grp;
            const int row1 = row0 + 8;
            if (j0 + 63 > q0) {
#pragma unroll
                for (int n = 0; n < 8; n++) {
                    const int c = j0 + 8 * n + tig * 2;
                    if (c > row0)     sacc[n][0] = -1e30f;
                    if (c + 1 > row0) sacc[n][1] = -1e30f;
                    if (c > row1)     sacc[n][2] = -1e30f;
                    if (c + 1 > row1) sacc[n][3] = -1e30f;
                }
            }

            float mx0 = -1e30f, mx1 = -1e30f;
#pragma unroll
            for (int n = 0; n < 8; n++) {
                mx0 = fmaxf(mx0, fmaxf(sacc[n][0], sacc[n][1]));
                mx1 = fmaxf(mx1, fmaxf(sacc[n][2], sacc[n][3]));
            }
            mx0 = fmaxf(mx0, __shfl_xor_sync(0xffffffffu, mx0, 1));
            mx0 = fmaxf(mx0, __shfl_xor_sync(0xffffffffu, mx0, 2));
            mx1 = fmaxf(mx1, __shfl_xor_sync(0xffffffffu, mx1, 1));
            mx1 = fmaxf(mx1, __shfl_xor_sync(0xffffffffu, mx1, 2));

            const float mn0 = fmaxf(m0r, mx0);
            const float mn1 = fmaxf(m1r, mx1);
            const float fi0 = ex2_(m0r - mn0);
            const float fi1 = ex2_(m1r - mn1);
            m0r = mn0; m1r = mn1;

            float sum0 = 0.f, sum1 = 0.f;
#pragma unroll
            for (int n = 0; n < 8; n++) {
                sacc[n][0] = ex2_(sacc[n][0] - mn0);
                sacc[n][1] = ex2_(sacc[n][1] - mn0);
                sacc[n][2] = ex2_(sacc[n][2] - mn1);
                sacc[n][3] = ex2_(sacc[n][3] - mn1);
                sum0 += sacc[n][0] + sacc[n][1];
                sum1 += sacc[n][2] + sacc[n][3];
            }
            sum0 += __shfl_xor_sync(0xffffffffu, sum0, 1);
            sum0 += __shfl_xor_sync(0xffffffffu, sum0, 2);
            sum1 += __shfl_xor_sync(0xffffffffu, sum1, 1);
            sum1 += __shfl_xor_sync(0xffffffffu, sum1, 2);
            l0 = l0 * fi0 + sum0;
            l1 = l1 * fi1 + sum1;

#pragma unroll
            for (int n = 0; n < 8; n++) {
                oacc[n][0] *= fi0; oacc[n][1] *= fi0;
                oacc[n][2] *= fi1; oacc[n][3] *= fi1;
            }

#pragma unroll
            for (int jj = 0; jj < 4; jj++) {
                const uint32_t p00 = __float_as_uint(sacc[2 * jj][0]);
                const uint32_t p01 = __float_as_uint(sacc[2 * jj][1]);
                const uint32_t p02 = __float_as_uint(sacc[2 * jj][2]);
                const uint32_t p03 = __float_as_uint(sacc[2 * jj][3]);
                const uint32_t p10 = __float_as_uint(sacc[2 * jj + 1][0]);
                const uint32_t p11 = __float_as_uint(sacc[2 * jj + 1][1]);
                const uint32_t p12 = __float_as_uint(sacc[2 * jj + 1][2]);
                const uint32_t p13 = __float_as_uint(sacc[2 * jj + 1][3]);

                const uint32_t ph0 = prmt_hi(p00, p01);
                const uint32_t ph1 = prmt_hi(p02, p03);
                const uint32_t ph2 = prmt_hi(p10, p11);
                const uint32_t ph3 = prmt_hi(p12, p13);
                const uint32_t pl0 = cvt_bf16x2(
                    sacc[2 * jj][1] - __uint_as_float(p01 & 0xffff0000u),
                    sacc[2 * jj][0] - __uint_as_float(p00 & 0xffff0000u));
                const uint32_t pl1 = cvt_bf16x2(
                    sacc[2 * jj][3] - __uint_as_float(p03 & 0xffff0000u),
                    sacc[2 * jj][2] - __uint_as_float(p02 & 0xffff0000u));
                const uint32_t pl2 = cvt_bf16x2(
                    sacc[2 * jj + 1][1] - __uint_as_float(p11 & 0xffff0000u),
                    sacc[2 * jj + 1][0] - __uint_as_float(p10 & 0xffff0000u));
                const uint32_t pl3 = cvt_bf16x2(
                    sacc[2 * jj + 1][3] - __uint_as_float(p13 & 0xffff0000u),
                    sacc[2 * jj + 1][2] - __uint_as_float(p12 & 0xffff0000u));

#pragma unroll
                for (int n = 0; n < 8; n++) {
                    const int vb = (8 * n + grp) * STR + 8 * jj + tig;
                    mma_bf16(oacc[n][0], oacc[n][1], oacc[n][2], oacc[n][3],
                             ph0, ph1, ph2, ph3, vh[vb], vh[vb + 4]);
                }
#pragma unroll
                for (int n = 0; n < 8; n++) {
                    const int vb = (8 * n + grp) * STR + 8 * jj + tig;
                    mma_bf16(oacc[n][0], oacc[n][1], oacc[n][2], oacc[n][3],
                             ph0, ph1, ph2, ph3, vl[vb], vl[vb + 4]);
                }
#pragma unroll
                for (int n = 0; n < 8; n++) {
                    const int vb = (8 * n + grp) * STR + 8 * jj + tig;
                    mma_bf16(oacc[n][0], oacc[n][1], oacc[n][2], oacc[n][3],
                             pl0, pl1, pl2, pl3, vh[vb], vh[vb + 4]);
                }
            }
        }
        __syncthreads();
    }

    const float inv0 = 1.f / l0;
    const float inv1 = 1.f / l1;
    const int row0 = q0 + wid * 16 + grp;
#pragma unroll
    for (int n = 0; n < 8; n++) {
        const int col = h * 64 + 8 * n + tig * 2;
        *(float2*)&g_ctx[(size_t)(b * S_ + row0) * D_ + col] =
            make_float2(oacc[n][0] * inv0, oacc[n][1] * inv0);
        *(float2*)&g_ctx[(size_t)(b * S_ + row0 + 8) * D_ + col] =
            make_float2(oacc[n][2] * inv1, oacc[n][3] * inv1);
    }
}

// ---------------------------------------------------------------------------
extern "C" void kernel_launch(void* const* d_in, const int* in_sizes, int n_in,
                              void* d_out, int out_size) {
    const float* x      = (const float*)d_in[0];
    const float* W_attn = (const float*)d_in[1];
    const float* b_attn = (const float*)d_in[2];
    const float* W_proj = (const float*)d_in[3];
    const float* b_proj = (const float*)d_in[4];
    float* out = (float*)d_out;

    const int gemm_smem = 2 * ST_WORDS * (int)sizeof(uint32_t);  // 73728
    cudaFuncSetAttribute(tc_gemm<3072, 0>, cudaFuncAttributeMaxDynamicSharedMemorySize,
                         gemm_smem);
    cudaFuncSetAttribute(tc_gemm<1024, 1>, cudaFuncAttributeMaxDynamicSharedMemorySize,
                         gemm_smem);

    const int flash_smem = (128 * STR * 2 + 64 * STR * 4) * (int)sizeof(uint32_t); // 73728
    cudaFuncSetAttribute(flash_tc, cudaFuncAttributeMaxDynamicSharedMemorySize,
                         flash_smem);

    tc_gemm<3072, 0><<<dim3(3072 / 128, 8192 / 256), 512, gemm_smem>>>(x, W_attn, b_attn, nullptr);
    flash_tc<<<dim3(S_ / 128, H_, B_), 256, flash_smem>>>();
    tc_gemm<1024, 1><<<dim3(1024 / 128, 8192 / 256), 512, gemm_smem>>>(nullptr, W_proj, b_proj, out);
}